// round 17
// baseline (speedup 1.0000x reference)
#include <cuda_runtime.h>
#include <cuda_fp16.h>
#include <cstdint>
#include <cstddef>

#define DEVI static __device__ __forceinline__

namespace li {

constexpr int B = 32, T = 1024, IN = 1024, OUT = 1024;
constexpr int TT = 128;                 // time rows per unit (GEMM M)
constexpr int TO = 128;                 // out cols per unit  (GEMM N)
constexpr int BKH = 64;                 // halves per K slab (= one 128B row)
constexpr int SLABS = IN / BKH;         // 16 slabs per unit
constexpr int TILES = T / TT;           // 8
constexpr int NSTRIPS = B * (OUT / TO); // 256
constexpr int NUNITS = NSTRIPS * TILES; // 2048
constexpr int PCTAS = 296;              // 148 SMs x 2 resident CTAs
constexpr int TOTAL_POPS = NUNITS + PCTAS;  // 2344; last pop resets counter

constexpr int STAGE_BYTES = (TT + TO) * 128;   // 32 KB (X 16K + W 16K, fp16)
constexpr int STG_STRIDE = 136;                // halves; conflict-free
constexpr int STAGING_OFF = 2 * STAGE_BYTES;   // 65536
constexpr int SMEM_DYN = STAGING_OFF + TT * STG_STRIDE * 2;  // 100352

__device__ __align__(16) __half g_Xh[(size_t)B * T * IN];   // 64MB scratch
__device__ __align__(16) __half g_Wh[(size_t)OUT * IN];     // 2MB scratch
__device__ int g_unit;                       // work-queue counter, self-reset
__device__ int g_cf[NSTRIPS * TILES];        // carry flags: 1 arrive + 1 consume
__device__ float g_carry[NSTRIPS * TILES * TT];  // u at end of (strip,tile)

DEVI uint32_t s2u(const void* p) {
  uint32_t a;
  asm("{ .reg .u64 t; cvta.to.shared.u64 t, %1; cvt.u32.u64 %0, t; }"
      : "=r"(a) : "l"(p));
  return a;
}
DEVI void cp16(uint32_t s, const void* g) {
  asm volatile("cp.async.cg.shared.global [%0], [%1], 16;" :: "r"(s), "l"(g)
               : "memory");
}
DEVI void cp_commit() { asm volatile("cp.async.commit_group;" ::: "memory"); }
DEVI void cp_wait0() { asm volatile("cp.async.wait_group 0;" ::: "memory"); }

DEVI void ldsm4(uint32_t* r, uint32_t a) {
  asm volatile("ldmatrix.sync.aligned.m8n8.x4.shared.b16 {%0,%1,%2,%3}, [%4];"
               : "=r"(r[0]), "=r"(r[1]), "=r"(r[2]), "=r"(r[3]) : "r"(a));
}
DEVI void mma16(float* c, const uint32_t* a, const uint32_t* b) {
  asm volatile(
      "mma.sync.aligned.m16n8k16.row.col.f32.f16.f16.f32 "
      "{%0,%1,%2,%3}, {%4,%5,%6,%7}, {%8,%9}, {%0,%1,%2,%3};"
      : "+f"(c[0]), "+f"(c[1]), "+f"(c[2]), "+f"(c[3])
      : "r"(a[0]), "r"(a[1]), "r"(a[2]), "r"(a[3]), "r"(b[0]), "r"(b[1]));
}
DEVI uint32_t packh2(float lo, float hi) {
  uint32_t d;
  asm("cvt.rn.f16x2.f32 %0, %1, %2;" : "=r"(d) : "f"(hi), "f"(lo));
  return d;
}
DEVI uint4 cvt8(float4 a, float4 b) {
  uint4 u;
  u.x = packh2(a.x, a.y);
  u.y = packh2(a.z, a.w);
  u.z = packh2(b.x, b.y);
  u.w = packh2(b.z, b.w);
  return u;
}
DEVI int ld_acq(const int* p) {
  int v;
  asm volatile("ld.acquire.gpu.global.b32 %0, [%1];" : "=r"(v) : "l"(p));
  return v;
}
DEVI void arrive_rel(int* p) {
  int o;
  asm volatile("atom.release.gpu.global.add.s32 %0, [%1], 1;"
               : "=r"(o) : "l"(p) : "memory");
}

// ---------------- pre-pass: fp32 -> fp16 (exact cover, DRAM-bound) -----------
__global__ void __launch_bounds__(256) cvt_kernel(const float4* __restrict__ X,
                                                  const float4* __restrict__ W) {
  uint4* xo = reinterpret_cast<uint4*>(g_Xh);
  uint4* wo = reinterpret_cast<uint4*>(g_Wh);
  const int gtid = blockIdx.x * 256 + threadIdx.x;  // 0..524287
#pragma unroll
  for (int it = 0; it < 8; ++it) {
    const size_t i = (size_t)it * 524288 + (size_t)gtid;
    xo[i] = cvt8(X[2 * i], X[2 * i + 1]);
  }
  if (gtid < 131072) {
    const size_t i = (size_t)gtid;
    wo[i] = cvt8(W[2 * i], W[2 * i + 1]);
  }
}

// ---------------- persistent fused GEMM + carry-linked scan ------------------
// 296 persistent CTAs pop 2048 (strip,tile) units tile-major; GEMMs are
// independent, scans chain through a global carry buffer per strip.
__global__ void __launch_bounds__(128, 2)
li_kernel(const float* __restrict__ bias, const float* __restrict__ decay,
          float* __restrict__ out) {
  extern __shared__ __align__(16) char dsm[];
  __shared__ int s_unit;
  const uint32_t sbase = s2u(dsm);

  const int tid = threadIdx.x;
  const int wid = tid >> 5;
  const int lane = tid & 31;

  // ---- unit-invariant constants ----
  const int lr = tid >> 3;
  const int lc = tid & 7;
  const uint32_t sw_off = (uint32_t)lr * 128 + (uint32_t)((lc ^ (lr & 7)) << 4);
  const int warp_m = wid >> 1, warp_n = wid & 1;
  const int r = lane & 7;
  const int khA = lane >> 4;
  const int khB = (lane >> 3) & 1;
  const uint32_t aBase =
      (uint32_t)(warp_m * 64 + ((lane >> 3) & 1) * 8 + r) * 128;
  const uint32_t bBase =
      (uint32_t)(TT * 128) +
      (uint32_t)(warp_n * 64 + ((lane >> 4) << 3) + r) * 128;

  auto pop = [&]() -> int {
    if (tid == 0) {
      const int u = atomicAdd(&g_unit, 1);
      if (u == TOTAL_POPS - 1) atomicExch(&g_unit, 0);  // last pop resets
      s_unit = u;
    }
    __syncthreads();
    return s_unit;
  };

  // issue slab `ks` of unit (ubb, uo0, ut0) into buffer ks&1
  auto load_slab_u = [&](int ubb, int uo0, int ut0, int ks) {
    const int k0 = ks * BKH;
    const uint32_t sb = sbase + (uint32_t)(ks & 1) * STAGE_BYTES;
    const __half* Xg = g_Xh + ((size_t)ubb * T + ut0 + lr) * IN + k0 + lc * 8;
    const __half* Ws = g_Wh + (size_t)(uo0 + lr) * IN + k0 + lc * 8;
#pragma unroll
    for (int i = 0; i < 8; ++i)
      cp16(sb + sw_off + (uint32_t)i * 2048, Xg + (size_t)i * 16 * IN);
#pragma unroll
    for (int i = 0; i < 8; ++i)
      cp16(sb + (uint32_t)(TT * 128) + sw_off + (uint32_t)i * 2048,
           Ws + (size_t)i * 16 * IN);
  };

  float acc[4][8][4];

  int unit = pop();
  if (unit < NUNITS) {
    const int strip0 = unit & 255;
    load_slab_u(strip0 >> 3, (strip0 & 7) * TO, (unit >> 8) * TT, 0);
    cp_commit();
  }

  while (unit < NUNITS) {
    const int tile = unit >> 8;
    const int strip = unit & 255;
    const int bb = strip >> 3;
    const int o0 = (strip & 7) * TO;
    const int t0 = tile * TT;

    const float dcy = decay[o0 + tid];
    const float omd = 1.0f - dcy;
    const float bo = bias[o0 + tid];

#pragma unroll
    for (int mf = 0; mf < 4; ++mf)
#pragma unroll
      for (int nf = 0; nf < 8; ++nf)
#pragma unroll
        for (int j = 0; j < 4; ++j) acc[mf][nf][j] = 0.f;

    for (int ks = 0; ks < SLABS; ++ks) {
      cp_wait0();
      __syncthreads();
      const uint32_t sb = sbase + (uint32_t)(ks & 1) * STAGE_BYTES;

      // kc-pipelined fragment loads + MMAs (R8, proven)
      uint32_t A[2][4][4], Bf[2][4][4];
      {
        const uint32_t swA = (uint32_t)((khA ^ r) << 4);
        const uint32_t swB = (uint32_t)((khB ^ r) << 4);
#pragma unroll
        for (int mf = 0; mf < 4; ++mf)
          ldsm4(A[0][mf], sb + aBase + (uint32_t)mf * 2048 + swA);
#pragma unroll
        for (int p = 0; p < 4; ++p)
          ldsm4(Bf[0][p], sb + bBase + (uint32_t)p * 2048 + swB);
      }
      if (ks + 1 < SLABS) {
        load_slab_u(bb, o0, t0, ks + 1);
        cp_commit();
      }
#pragma unroll
      for (int kc = 0; kc < 4; ++kc) {
        const int pb = kc & 1;
        if (kc < 3) {
          const uint32_t swA = (uint32_t)(((2 * (kc + 1) + khA) ^ r) << 4);
          const uint32_t swB = (uint32_t)(((2 * (kc + 1) + khB) ^ r) << 4);
#pragma unroll
          for (int mf = 0; mf < 4; ++mf)
            ldsm4(A[pb ^ 1][mf], sb + aBase + (uint32_t)mf * 2048 + swA);
#pragma unroll
          for (int p = 0; p < 4; ++p)
            ldsm4(Bf[pb ^ 1][p], sb + bBase + (uint32_t)p * 2048 + swB);
        }
#pragma unroll
        for (int mf = 0; mf < 4; ++mf)
#pragma unroll
          for (int nf = 0; nf < 8; ++nf)
            mma16(acc[mf][nf], A[pb][mf], &Bf[pb][nf >> 1][(nf & 1) * 2]);
      }
    }

    // ---- epilogue: fragments -> fp16 staging [t][o] ----
    __syncthreads();  // prior scan's staging reads are complete
    unsigned* stg_u = reinterpret_cast<unsigned*>(dsm + STAGING_OFF);
#pragma unroll
    for (int mf = 0; mf < 4; ++mf)
#pragma unroll
      for (int nf = 0; nf < 8; ++nf) {
        const int row = warp_m * 64 + mf * 16 + (lane >> 2);
        const int col = warp_n * 64 + nf * 8 + 2 * (lane & 3);
        stg_u[(row * STG_STRIDE + col) >> 1] =
            packh2(acc[mf][nf][0], acc[mf][nf][1]);
        stg_u[((row + 8) * STG_STRIDE + col) >> 1] =
            packh2(acc[mf][nf][2], acc[mf][nf][3]);
      }
    __syncthreads();

    // ---- pop next unit and prefetch its slab 0 (hidden under the scan) ----
    const int next = pop();
    if (next < NUNITS) {
      const int ns = next & 255;
      load_slab_u(ns >> 3, (ns & 7) * TO, (next >> 8) * TT, 0);
      cp_commit();
    }

    // ---- carry in: wait for (strip, tile-1) scan ----
    float u = 0.f;
    if (tile > 0) {
      int* f = &g_cf[strip * TILES + tile - 1];
      if (tid == 0) {
        while (ld_acq(f) < 1) __nanosleep(64);
        const int old = atomicAdd(f, 1);
        if (old == 1) atomicExch(f, 0);  // 1 arrive + 1 consume -> reset
      }
      __syncthreads();
      u = g_carry[(size_t)(strip * TILES + tile - 1) * TT + tid];
    }

    // ---- scan this tile; publish carry for the next ----
    {
      const __half* sh = reinterpret_cast<const __half*>(dsm + STAGING_OFF);
      float* ob = out + ((size_t)bb * T + t0) * OUT + o0 + tid;
#pragma unroll 8
      for (int t = 0; t < TT; ++t) {
        const float x = __half2float(sh[t * STG_STRIDE + tid]) + bo;
        u = fmaf(dcy, u, omd * x);
        ob[(size_t)t * OUT] = u;
      }
    }
    if (tile + 1 < TILES) {
      g_carry[(size_t)(strip * TILES + tile) * TT + tid] = u;
      __threadfence();
      __syncthreads();
      if (tid == 0) arrive_rel(&g_cf[strip * TILES + tile]);
    }

    unit = next;
  }
}

}  // namespace li

extern "C" void kernel_launch(void* const* d_in, const int* in_sizes, int n_in,
                              void* d_out, int out_size) {
  const float* X = (const float*)d_in[0];      // [B,T,IN]
  const float* W = (const float*)d_in[1];      // [OUT,IN]
  const float* bias = (const float*)d_in[2];   // [OUT]
  const float* decay = (const float*)d_in[3];  // [OUT]
  float* out = (float*)d_out;                  // [B,T,OUT]

  static bool init = false;
  if (!init) {
    cudaFuncSetAttribute(li::li_kernel,
                         cudaFuncAttributeMaxDynamicSharedMemorySize,
                         li::SMEM_DYN);
    init = true;
  }
  li::cvt_kernel<<<2048, 256>>>((const float4*)X, (const float4*)W);
  li::li_kernel<<<li::PCTAS, 128, li::SMEM_DYN>>>(bias, decay, out);
}